// round 12
// baseline (speedup 1.0000x reference)
#include <cuda_runtime.h>
#include <cuda_bf16.h>
#include <stdint.h>
#include <math.h>

typedef unsigned int u32;
typedef unsigned long long u64;
typedef unsigned char u8;
typedef unsigned short u16;

// Problem constants: x[B=4,S=12,N=4096,C=64], A[4096,4096], W[H=128,C=64]
#define NB 4
#define NS 12
#define BS 48
#define NN 4096
#define CC 64
#define HH 128
#define PP (BS*CC)     // 3072

// fp8 scaling: A stored as 16*A, Xd stored as 64*d*x -> Z_raw = 1024*Z
#define ASCALE 16.0f
#define BSCALE 64.0f
#define ZDESCALE (1.0f/1024.0f)

// Scratch (device globals; allocation-free rule)
__device__ float g_d[NN];
__device__ u8 g_a8[(u64)NN * NN];                  // A e4m3 (x16)        16.8 MB
__device__ u8 g_xdT8[(u64)PP * NN];                // XdT[p][k] e4m3(x64) 12.6 MB
__device__ __nv_bfloat16 g_z16[(u64)NN * PP];      // Z bf16 (descaled)   25 MB

__device__ __forceinline__ u32 s2u(const void* p) {
    u32 r;
    asm("{.reg .u64 t; cvta.to.shared.u64 t, %1; cvt.u32.u64 %0, t;}" : "=r"(r) : "l"(p));
    return r;
}
__device__ __forceinline__ void cpasync16(u32 dst, const void* src) {
    asm volatile("cp.async.cg.shared.global [%0], [%1], 16;" :: "r"(dst), "l"(src) : "memory");
}
__device__ __forceinline__ u32 packbf2(float a, float b) {
    __nv_bfloat162 v = __floats2bfloat162_rn(a, b);
    return *reinterpret_cast<u32*>(&v);
}
__device__ __forceinline__ u32 f2tf32(float f) {
    u32 r;
    asm("cvt.rna.tf32.f32 %0, %1;" : "=r"(r) : "f"(f));
    return r;
}
// pack 4 floats -> 4 e4m3 bytes (byte0 = a ... byte3 = d)
__device__ __forceinline__ u32 pack4_e4m3(float a, float b, float c, float d) {
    u16 lo, hi;
    asm("cvt.rn.satfinite.e4m3x2.f32 %0, %1, %2;" : "=h"(lo) : "f"(b), "f"(a));
    asm("cvt.rn.satfinite.e4m3x2.f32 %0, %1, %2;" : "=h"(hi) : "f"(d), "f"(c));
    return (u32)lo | ((u32)hi << 16);
}

// ---------------------------------------------------------------------------
// 1) Fused pass over A: rowsum->d, A->e4m3(x16), A->output tail
// ---------------------------------------------------------------------------
__global__ void __launch_bounds__(256) fusedA_kernel(const float* __restrict__ A,
                                                     float* __restrict__ outtail,
                                                     int do_copy) {
    const int row = blockIdx.x;
    const float4* a4 = reinterpret_cast<const float4*>(A + (u64)row * NN);
    float4*       o4 = reinterpret_cast<float4*>(outtail + (u64)row * NN);
    u32*          a8 = reinterpret_cast<u32*>(g_a8 + (u64)row * NN);

    float s = 0.f;
    for (int i = threadIdx.x; i < NN / 4; i += 256) {
        float4 v = a4[i];
        if (do_copy) o4[i] = v;
        a8[i] = pack4_e4m3(v.x * ASCALE, v.y * ASCALE, v.z * ASCALE, v.w * ASCALE);
        s += (v.x + v.y) + (v.z + v.w);
    }
    __shared__ float red[8];
    for (int off = 16; off > 0; off >>= 1) s += __shfl_down_sync(0xffffffffu, s, off);
    if ((threadIdx.x & 31) == 0) red[threadIdx.x >> 5] = s;
    __syncthreads();
    if (threadIdx.x == 0) {
        float t = red[0] + red[1] + red[2] + red[3] + red[4] + red[5] + red[6] + red[7];
        g_d[row] = rsqrtf(t + 1.0f);
    }
}

// ---------------------------------------------------------------------------
// 2) XdT8[p][k] = e4m3( 64 * d[k] * x[bs,k,c] ),  p = bs*64+c.  SMEM transpose.
// ---------------------------------------------------------------------------
__global__ void __launch_bounds__(256) build_xdT_kernel(const float* __restrict__ x) {
    __shared__ float sm[64][65];
    const int tid = threadIdx.x;
    const int j0 = blockIdx.x * 64;
    const int bs = blockIdx.y;

    #pragma unroll
    for (int i = 0; i < 4; i++) {
        int f = tid + 256 * i;              // 0..1023 float4
        int r = f >> 4, c4 = f & 15;
        float4 v = reinterpret_cast<const float4*>(x)[((u64)bs * NN + j0 + r) * (CC / 4) + c4];
        float dj = g_d[j0 + r] * BSCALE;
        sm[r][c4 * 4 + 0] = v.x * dj;
        sm[r][c4 * 4 + 1] = v.y * dj;
        sm[r][c4 * 4 + 2] = v.z * dj;
        sm[r][c4 * 4 + 3] = v.w * dj;
    }
    __syncthreads();

    #pragma unroll
    for (int i = 0; i < 4; i++) {
        int f = tid + 256 * i;              // 0..1023 groups of 4 fp8
        int c = f >> 4, j4 = f & 15;
        u32 o = pack4_e4m3(sm[j4 * 4 + 0][c], sm[j4 * 4 + 1][c],
                           sm[j4 * 4 + 2][c], sm[j4 * 4 + 3][c]);
        u8* dst = g_xdT8 + (u64)(bs * 64 + c) * NN + j0 + j4 * 4;
        *reinterpret_cast<u32*>(dst) = o;
    }
}

// ---------------------------------------------------------------------------
// 3) GEMM1: Z = A8 @ XdT8^T  (e4m3 mma.sync m16n8k32, fp32 accum)
//    128x128x64 tiles, 8 warps (2Mx4N), 3-stage cp.async, Z stored bf16
//    SMEM rows of 64 B (= 64 fp8 k-values), swizzle c^((row>>1)&3) — layout
//    is byte-identical to the bf16 BK=32 kernel (16-bit unit = fp8 pair).
// ---------------------------------------------------------------------------
#define BK 64
#define NSTG 3
#define A_STG (128*64)             // 8192 B
#define B_STG (128*64)             // 8192 B
#define STG (A_STG + B_STG)        // 16384 B
#define NCHUNK (NN / BK)           // 64
#define GEMM_DYN (NSTG * STG)      // 49152 B

__device__ __forceinline__ void load_chunk(int j, int tid, u32 sbase,
                                           const u8* Abase, const u8* Bbase) {
    int s = j % NSTG;
    u32 sA = sbase + (u32)(s * STG);
    u32 sB = sA + A_STG;
    int k0 = j * BK;                       // byte offset (1 B per k)
    #pragma unroll
    for (int i = 0; i < 2; i++) {           // A: 128 rows x 4 x 16B
        int idx = tid + 256 * i;
        int row = idx >> 2, c = idx & 3;
        cpasync16(sA + (u32)(row * 64) + ((u32)(c ^ ((row >> 1) & 3)) << 4),
                  Abase + (u64)row * NN + k0 + c * 16);
    }
    #pragma unroll
    for (int i = 0; i < 2; i++) {           // B: 128 rows x 4 x 16B
        int idx = tid + 256 * i;
        int row = idx >> 2, c = idx & 3;
        cpasync16(sB + (u32)(row * 64) + ((u32)(c ^ ((row >> 1) & 3)) << 4),
                  Bbase + (u64)row * NN + k0 + c * 16);
    }
}

__global__ void __launch_bounds__(256, 2) gemm1_kernel() {
    extern __shared__ __align__(16) char dsm[];
    const int tid  = threadIdx.x;
    const int lane = tid & 31, wid = tid >> 5;
    const int warpM = wid >> 2, warpN = wid & 3;     // 2 x 4 warps
    const int bn0 = blockIdx.x * 128;
    const int bm0 = blockIdx.y * 128;

    const u32 sbase = s2u(dsm);
    const u8* Abase = g_a8   + (u64)bm0 * NN;
    const u8* Bbase = g_xdT8 + (u64)bn0 * NN;

    // ldmatrix lane offsets (16-bit-unit view: 32 units/row, mma k-step = 16 units = 32 B)
    const int g = lane >> 3, lr = lane & 7;
    u32 aOff[4][2], bOff[2][2];
    #pragma unroll
    for (int i = 0; i < 4; i++) {
        int m = warpM * 64 + i * 16 + (g & 1) * 8 + lr;
        #pragma unroll
        for (int ks = 0; ks < 2; ks++) {
            int ch = 2 * ks + (g >> 1);
            aOff[i][ks] = (u32)(m * 64) + ((u32)(ch ^ ((m >> 1) & 3)) << 4);
        }
    }
    #pragma unroll
    for (int nb = 0; nb < 2; nb++) {
        int n = warpN * 32 + nb * 16 + (g >> 1) * 8 + lr;
        #pragma unroll
        for (int ks = 0; ks < 2; ks++) {
            int ch = 2 * ks + (g & 1);
            bOff[nb][ks] = (u32)A_STG + (u32)(n * 64) + ((u32)(ch ^ ((n >> 1) & 3)) << 4);
        }
    }

    float acc[4][4][4];
    #pragma unroll
    for (int i = 0; i < 4; i++)
        #pragma unroll
        for (int j = 0; j < 4; j++)
            #pragma unroll
            for (int q = 0; q < 4; q++) acc[i][j][q] = 0.f;

    // prologue: chunks 0,1
    load_chunk(0, tid, sbase, Abase, Bbase);
    asm volatile("cp.async.commit_group;" ::: "memory");
    load_chunk(1, tid, sbase, Abase, Bbase);
    asm volatile("cp.async.commit_group;" ::: "memory");

    int stage = 0;
    #pragma unroll 1
    for (int it = 0; it < NCHUNK; ++it) {
        if (it < NCHUNK - 2) asm volatile("cp.async.wait_group 1;" ::: "memory");
        else                 asm volatile("cp.async.wait_group 0;" ::: "memory");
        __syncthreads();
        const u32 sb = sbase + (u32)(stage * STG);

        #pragma unroll
        for (int ks = 0; ks < 2; ks++) {
            u32 af[4][4];
            u32 bfr[4][2];
            #pragma unroll
            for (int i = 0; i < 4; i++)
                asm volatile("ldmatrix.sync.aligned.m8n8.x4.shared.b16 {%0,%1,%2,%3}, [%4];"
                    : "=r"(af[i][0]), "=r"(af[i][1]), "=r"(af[i][2]), "=r"(af[i][3])
                    : "r"(sb + aOff[i][ks]));
            #pragma unroll
            for (int nb = 0; nb < 2; nb++) {
                u32 r0, r1, r2, r3;
                asm volatile("ldmatrix.sync.aligned.m8n8.x4.shared.b16 {%0,%1,%2,%3}, [%4];"
                    : "=r"(r0), "=r"(r1), "=r"(r2), "=r"(r3)
                    : "r"(sb + bOff[nb][ks]));
                bfr[2*nb][0]   = r0; bfr[2*nb][1]   = r1;
                bfr[2*nb+1][0] = r2; bfr[2*nb+1][1] = r3;
            }
            #pragma unroll
            for (int i = 0; i < 4; i++)
                #pragma unroll
                for (int j = 0; j < 4; j++)
                    asm volatile("mma.sync.aligned.m16n8k32.row.col.f32.e4m3.e4m3.f32 "
                        "{%0,%1,%2,%3}, {%4,%5,%6,%7}, {%8,%9}, {%0,%1,%2,%3};"
                        : "+f"(acc[i][j][0]), "+f"(acc[i][j][1]),
                          "+f"(acc[i][j][2]), "+f"(acc[i][j][3])
                        : "r"(af[i][0]), "r"(af[i][1]), "r"(af[i][2]), "r"(af[i][3]),
                          "r"(bfr[j][0]), "r"(bfr[j][1]));
        }

        if (it + 2 < NCHUNK) {
            load_chunk(it + 2, tid, sbase, Abase, Bbase);
            asm volatile("cp.async.commit_group;" ::: "memory");
        }
        if (++stage == NSTG) stage = 0;
    }

    // store Z (bf16, descaled)
    #pragma unroll
    for (int i = 0; i < 4; i++) {
        int r0 = bm0 + warpM * 64 + i * 16 + (lane >> 2);
        #pragma unroll
        for (int j = 0; j < 4; j++) {
            int c = bn0 + warpN * 32 + j * 8 + (lane & 3) * 2;
            *reinterpret_cast<u32*>(g_z16 + (u64)r0 * PP + c)
                = packbf2(acc[i][j][0] * ZDESCALE, acc[i][j][1] * ZDESCALE);
            *reinterpret_cast<u32*>(g_z16 + (u64)(r0 + 8) * PP + c)
                = packbf2(acc[i][j][2] * ZDESCALE, acc[i][j][3] * ZDESCALE);
        }
    }
}

// ---------------------------------------------------------------------------
// 4) Epilogue via tf32 tensor cores (unchanged from R10)
// ---------------------------------------------------------------------------
#define EP_PAD 68
#define EPI_DYN ((128*EP_PAD + 128*EP_PAD) * 4)

__global__ void __launch_bounds__(256) epilogue_kernel(const float* __restrict__ x,
                                                       const float* __restrict__ W,
                                                       float* __restrict__ out) {
    extern __shared__ __align__(16) u32 esm[];
    u32* sT = esm;
    u32* sW = esm + 128 * EP_PAD;

    const int tid  = threadIdx.x;
    const int lane = tid & 31, wid = tid >> 5;
    const int i0   = blockIdx.x * 128;
    const int bs   = blockIdx.y;

    for (int k = tid; k < 2048; k += 256) {
        int h = k >> 4, c4 = k & 15;
        float4 v = reinterpret_cast<const float4*>(W)[(u64)h * 16 + c4];
        u32* d = sW + h * EP_PAD + c4 * 4;
        d[0] = f2tf32(v.x); d[1] = f2tf32(v.y); d[2] = f2tf32(v.z); d[3] = f2tf32(v.w);
    }
    for (int k = tid; k < 2048; k += 256) {
        int r = k >> 4, c4 = k & 15;
        int i = i0 + r;
        float4 xv = reinterpret_cast<const float4*>(x)[((u64)bs * NN + i) * 16 + c4];
        uint2 zr = *reinterpret_cast<const uint2*>(g_z16 + (u64)i * PP + bs * CC + c4 * 4);
        __nv_bfloat162 zlo = *reinterpret_cast<__nv_bfloat162*>(&zr.x);
        __nv_bfloat162 zhi = *reinterpret_cast<__nv_bfloat162*>(&zr.y);
        float di = g_d[i];
        u32* d = sT + r * EP_PAD + c4 * 4;
        d[0] = f2tf32(xv.x - di * __bfloat162float(zlo.x));
        d[1] = f2tf32(xv.y - di * __bfloat162float(zlo.y));
        d[2] = f2tf32(xv.z - di * __bfloat162float(zhi.x));
        d[3] = f2tf32(xv.w - di * __bfloat162float(zhi.y));
    }
    __syncthreads();

    const int gq = lane >> 2;
    const int tq = lane & 3;
    float acc[16][4];
    #pragma unroll
    for (int nt = 0; nt < 16; nt++)
        #pragma unroll
        for (int q = 0; q < 4; q++) acc[nt][q] = 0.f;

    const u32* tRow0 = sT + (wid * 16 + gq) * EP_PAD;
    const u32* tRow8 = tRow0 + 8 * EP_PAD;

    #pragma unroll
    for (int ks = 0; ks < 8; ks++) {
        int k0 = ks * 8 + tq;
        u32 a0 = tRow0[k0];
        u32 a1 = tRow8[k0];
        u32 a2 = tRow0[k0 + 4];
        u32 a3 = tRow8[k0 + 4];
        #pragma unroll
        for (int nt = 0; nt < 16; nt++) {
            const u32* wRow = sW + (nt * 8 + gq) * EP_PAD;
            u32 b0 = wRow[ks * 8 + tq];
            u32 b1 = wRow[ks * 8 + tq + 4];
            asm volatile("mma.sync.aligned.m16n8k8.row.col.f32.tf32.tf32.f32 "
                "{%0,%1,%2,%3}, {%4,%5,%6,%7}, {%8,%9}, {%0,%1,%2,%3};"
                : "+f"(acc[nt][0]), "+f"(acc[nt][1]), "+f"(acc[nt][2]), "+f"(acc[nt][3])
                : "r"(a0), "r"(a1), "r"(a2), "r"(a3), "r"(b0), "r"(b1));
        }
    }

    const int iA = i0 + wid * 16 + gq;
    float* oA = out + ((u64)bs * NN + iA) * HH + tq * 2;
    float* oB = oA + (u64)8 * HH;
    #pragma unroll
    for (int nt = 0; nt < 16; nt++) {
        float2 v0, v1;
        v0.x = 1.0f / (1.0f + __expf(-acc[nt][0]));
        v0.y = 1.0f / (1.0f + __expf(-acc[nt][1]));
        v1.x = 1.0f / (1.0f + __expf(-acc[nt][2]));
        v1.y = 1.0f / (1.0f + __expf(-acc[nt][3]));
        *reinterpret_cast<float2*>(oA + nt * 8) = v0;
        *reinterpret_cast<float2*>(oB + nt * 8) = v1;
    }
}

// ---------------------------------------------------------------------------
extern "C" void kernel_launch(void* const* d_in, const int* in_sizes, int n_in,
                              void* d_out, int out_size) {
    const float* x = (const float*)d_in[0];
    const float* A = (const float*)d_in[1];
    const float* W = (const float*)d_in[2];
    float* out = (float*)d_out;

    const int out_elems = NB * NS * NN * HH;   // 25,165,824
    const int do_copy = (out_size >= out_elems + NN * NN) ? 1 : 0;
    float* tail = do_copy ? (out + out_elems) : (float*)g_z16;

    cudaFuncSetAttribute(gemm1_kernel,
                         cudaFuncAttributeMaxDynamicSharedMemorySize, GEMM_DYN);
    cudaFuncSetAttribute(epilogue_kernel,
                         cudaFuncAttributeMaxDynamicSharedMemorySize, EPI_DYN);

    fusedA_kernel<<<NN, 256>>>(A, tail, do_copy);

    {
        dim3 grid(NN / 64, BS);          // (64, 48)
        build_xdT_kernel<<<grid, 256>>>(x);
    }
    {
        dim3 grid(PP / 128, NN / 128);   // (24, 32)
        gemm1_kernel<<<grid, 256, GEMM_DYN>>>();
    }
    {
        dim3 grid(NN / 128, BS);         // (32, 48)
        epilogue_kernel<<<grid, 256, EPI_DYN>>>(x, W, out);
    }
}

// round 14
// speedup vs baseline: 1.0598x; 1.0598x over previous
#include <cuda_runtime.h>
#include <cuda_bf16.h>
#include <stdint.h>
#include <math.h>

typedef unsigned int u32;
typedef unsigned long long u64;

// Problem constants: x[B=4,S=12,N=4096,C=64], A[4096,4096], W[H=128,C=64]
#define NB 4
#define NS 12
#define BS 48
#define NN 4096
#define CC 64
#define HH 128
#define PP (BS*CC)     // 3072

// Scratch (device globals; allocation-free rule)
__device__ float g_d[NN];
__device__ __nv_bfloat16 g_a16[(u64)NN * NN];      // A bf16 row-major (K-contig)  33.5 MB
__device__ __nv_bfloat16 g_xdT[(u64)PP * NN];      // XdT[p][k] bf16 (K-contig)    25 MB

__device__ __forceinline__ u32 s2u(const void* p) {
    u32 r;
    asm("{.reg .u64 t; cvta.to.shared.u64 t, %1; cvt.u32.u64 %0, t;}" : "=r"(r) : "l"(p));
    return r;
}
__device__ __forceinline__ void cpasync16(u32 dst, const void* src) {
    asm volatile("cp.async.cg.shared.global [%0], [%1], 16;" :: "r"(dst), "l"(src) : "memory");
}
__device__ __forceinline__ u32 packbf2(float a, float b) {
    __nv_bfloat162 v = __floats2bfloat162_rn(a, b);
    return *reinterpret_cast<u32*>(&v);
}
__device__ __forceinline__ u32 f2tf32(float f) {
    u32 r;
    asm("cvt.rna.tf32.f32 %0, %1;" : "=r"(r) : "f"(f));
    return r;
}

// ---------------------------------------------------------------------------
// 1) Fused pass over A: rowsum->d, A->bf16, A->output tail
// ---------------------------------------------------------------------------
__global__ void __launch_bounds__(256) fusedA_kernel(const float* __restrict__ A,
                                                     float* __restrict__ outtail,
                                                     int do_copy) {
    const int row = blockIdx.x;
    const float4* a4 = reinterpret_cast<const float4*>(A + (u64)row * NN);
    float4*       o4 = reinterpret_cast<float4*>(outtail + (u64)row * NN);
    uint2*       a16 = reinterpret_cast<uint2*>(g_a16 + (u64)row * NN);

    float s = 0.f;
    for (int i = threadIdx.x; i < NN / 4; i += 256) {
        float4 v = a4[i];
        if (do_copy) o4[i] = v;
        uint2 o;
        o.x = packbf2(v.x, v.y);
        o.y = packbf2(v.z, v.w);
        a16[i] = o;
        s += (v.x + v.y) + (v.z + v.w);
    }
    __shared__ float red[8];
    for (int off = 16; off > 0; off >>= 1) s += __shfl_down_sync(0xffffffffu, s, off);
    if ((threadIdx.x & 31) == 0) red[threadIdx.x >> 5] = s;
    __syncthreads();
    if (threadIdx.x == 0) {
        float t = red[0] + red[1] + red[2] + red[3] + red[4] + red[5] + red[6] + red[7];
        g_d[row] = rsqrtf(t + 1.0f);
    }
}

// ---------------------------------------------------------------------------
// 2) XdT[p][k] = bf16( d[k] * x[bs,k,c] ),  p = bs*64+c.  SMEM transpose.
// ---------------------------------------------------------------------------
__global__ void __launch_bounds__(256) build_xdT_kernel(const float* __restrict__ x) {
    __shared__ float sm[64][65];
    const int tid = threadIdx.x;
    const int j0 = blockIdx.x * 64;
    const int bs = blockIdx.y;

    #pragma unroll
    for (int i = 0; i < 4; i++) {
        int f = tid + 256 * i;              // 0..1023 float4
        int r = f >> 4, c4 = f & 15;
        float4 v = reinterpret_cast<const float4*>(x)[((u64)bs * NN + j0 + r) * (CC / 4) + c4];
        float dj = g_d[j0 + r];
        sm[r][c4 * 4 + 0] = v.x * dj;
        sm[r][c4 * 4 + 1] = v.y * dj;
        sm[r][c4 * 4 + 2] = v.z * dj;
        sm[r][c4 * 4 + 3] = v.w * dj;
    }
    __syncthreads();

    #pragma unroll
    for (int i = 0; i < 4; i++) {
        int f = tid + 256 * i;              // 0..1023 groups of 4 bf16
        int c = f >> 4, j4 = f & 15;
        uint2 o;
        o.x = packbf2(sm[j4 * 4 + 0][c], sm[j4 * 4 + 1][c]);
        o.y = packbf2(sm[j4 * 4 + 2][c], sm[j4 * 4 + 3][c]);
        __nv_bfloat16* dst = g_xdT + (u64)(bs * 64 + c) * NN + j0 + j4 * 4;
        *reinterpret_cast<uint2*>(dst) = o;
    }
}

// ---------------------------------------------------------------------------
// 3) FUSED GEMM + epilogue:
//    Z_tile = A16 @ XdT^T   (bf16 mma.sync, 128x128x32, 3-stage cp.async)
//    then in-CTA: T = x - d*Z (tf32 smem), out = sigmoid(T @ W^T) (tf32 mma)
//    CTA (bn,bm) owns 2 bs x 128 i x all 128 h of the output.
// ---------------------------------------------------------------------------
#define BK 32
#define NSTG 3
#define A_STG (128*64)             // 8192 B
#define B_STG (128*64)             // 8192 B
#define STG (A_STG + B_STG)        // 16384 B
#define NCHUNK (NN / BK)           // 128
#define EP_PAD 68                  // T/W row stride in u32
#define SW_OFF (256*EP_PAD)        // u32 offset of W region (69632 B)
#define GEMM_DYN ((256*EP_PAD + 128*EP_PAD) * 4)   // 104448 B

__device__ __forceinline__ void load_chunk(int j, int tid, u32 sbase,
                                           const __nv_bfloat16* Abase,
                                           const __nv_bfloat16* Bbase) {
    int s = j % NSTG;
    u32 sA = sbase + (u32)(s * STG);
    u32 sB = sA + A_STG;
    int k0 = j * BK;
    #pragma unroll
    for (int i = 0; i < 2; i++) {           // A: 128 rows x 4 x 16B
        int idx = tid + 256 * i;
        int row = idx >> 2, c = idx & 3;
        cpasync16(sA + (u32)(row * 64) + ((u32)(c ^ ((row >> 1) & 3)) << 4),
                  Abase + (u64)row * NN + k0 + c * 8);
    }
    #pragma unroll
    for (int i = 0; i < 2; i++) {           // B: 128 rows x 4 x 16B
        int idx = tid + 256 * i;
        int row = idx >> 2, c = idx & 3;
        cpasync16(sB + (u32)(row * 64) + ((u32)(c ^ ((row >> 1) & 3)) << 4),
                  Bbase + (u64)row * NN + k0 + c * 8);
    }
}

__global__ void __launch_bounds__(256, 2) gemm_fused_kernel(const float* __restrict__ x,
                                                            const float* __restrict__ W,
                                                            float* __restrict__ out) {
    extern __shared__ __align__(16) char dsm[];
    __shared__ float sD[128];
    u32* esm = reinterpret_cast<u32*>(dsm);

    const int tid  = threadIdx.x;
    const int lane = tid & 31, wid = tid >> 5;
    const int warpM = wid >> 2, warpN = wid & 3;     // 2 x 4 warps
    const int bn0 = blockIdx.x * 128;
    const int bm0 = blockIdx.y * 128;

    const u32 sbase = s2u(dsm);
    const __nv_bfloat16* Abase = g_a16 + (u64)bm0 * NN;
    const __nv_bfloat16* Bbase = g_xdT + (u64)bn0 * NN;

    // d for this CTA's rows
    if (tid < 128) sD[tid] = g_d[bm0 + tid];

    // ldmatrix lane offsets
    const int g = lane >> 3, lr = lane & 7;
    u32 aOff[4][2], bOff[2][2];
    #pragma unroll
    for (int i = 0; i < 4; i++) {
        int m = warpM * 64 + i * 16 + (g & 1) * 8 + lr;
        #pragma unroll
        for (int ks = 0; ks < 2; ks++) {
            int ch = 2 * ks + (g >> 1);
            aOff[i][ks] = (u32)(m * 64) + ((u32)(ch ^ ((m >> 1) & 3)) << 4);
        }
    }
    #pragma unroll
    for (int nb = 0; nb < 2; nb++) {
        int n = warpN * 32 + nb * 16 + (g >> 1) * 8 + lr;
        #pragma unroll
        for (int ks = 0; ks < 2; ks++) {
            int ch = 2 * ks + (g & 1);
            bOff[nb][ks] = (u32)A_STG + (u32)(n * 64) + ((u32)(ch ^ ((n >> 1) & 3)) << 4);
        }
    }

    float acc[4][4][4];
    #pragma unroll
    for (int i = 0; i < 4; i++)
        #pragma unroll
        for (int j = 0; j < 4; j++)
            #pragma unroll
            for (int q = 0; q < 4; q++) acc[i][j][q] = 0.f;

    // prologue: chunks 0,1
    load_chunk(0, tid, sbase, Abase, Bbase);
    asm volatile("cp.async.commit_group;" ::: "memory");
    load_chunk(1, tid, sbase, Abase, Bbase);
    asm volatile("cp.async.commit_group;" ::: "memory");

    // Preload W (tf32) into the region beyond the pipeline stages — overlaps mainloop
    for (int k = tid; k < 2048; k += 256) {
        int h = k >> 4, c4 = k & 15;
        float4 v = reinterpret_cast<const float4*>(W)[(u64)h * 16 + c4];
        u32* d = esm + SW_OFF + h * EP_PAD + c4 * 4;
        d[0] = f2tf32(v.x); d[1] = f2tf32(v.y); d[2] = f2tf32(v.z); d[3] = f2tf32(v.w);
    }

    int stage = 0;
    #pragma unroll 1
    for (int it = 0; it < NCHUNK; ++it) {
        if (it < NCHUNK - 2) asm volatile("cp.async.wait_group 1;" ::: "memory");
        else                 asm volatile("cp.async.wait_group 0;" ::: "memory");
        __syncthreads();
        const u32 sb = sbase + (u32)(stage * STG);

        #pragma unroll
        for (int ks = 0; ks < 2; ks++) {
            u32 af[4][4];
            u32 bfr[4][2];
            #pragma unroll
            for (int i = 0; i < 4; i++)
                asm volatile("ldmatrix.sync.aligned.m8n8.x4.shared.b16 {%0,%1,%2,%3}, [%4];"
                    : "=r"(af[i][0]), "=r"(af[i][1]), "=r"(af[i][2]), "=r"(af[i][3])
                    : "r"(sb + aOff[i][ks]));
            #pragma unroll
            for (int nb = 0; nb < 2; nb++) {
                u32 r0, r1, r2, r3;
                asm volatile("ldmatrix.sync.aligned.m8n8.x4.shared.b16 {%0,%1,%2,%3}, [%4];"
                    : "=r"(r0), "=r"(r1), "=r"(r2), "=r"(r3)
                    : "r"(sb + bOff[nb][ks]));
                bfr[2*nb][0]   = r0; bfr[2*nb][1]   = r1;
                bfr[2*nb+1][0] = r2; bfr[2*nb+1][1] = r3;
            }
            #pragma unroll
            for (int i = 0; i < 4; i++)
                #pragma unroll
                for (int j = 0; j < 4; j++)
                    asm volatile("mma.sync.aligned.m16n8k16.row.col.f32.bf16.bf16.f32 "
                        "{%0,%1,%2,%3}, {%4,%5,%6,%7}, {%8,%9}, {%0,%1,%2,%3};"
                        : "+f"(acc[i][j][0]), "+f"(acc[i][j][1]),
                          "+f"(acc[i][j][2]), "+f"(acc[i][j][3])
                        : "r"(af[i][0]), "r"(af[i][1]), "r"(af[i][2]), "r"(af[i][3]),
                          "r"(bfr[j][0]), "r"(bfr[j][1]));
        }

        if (it + 2 < NCHUNK) {
            load_chunk(it + 2, tid, sbase, Abase, Bbase);
            asm volatile("cp.async.commit_group;" ::: "memory");
        }
        if (++stage == NSTG) stage = 0;
    }
    __syncthreads();   // all warps done reading pipeline stages

    // ---- Phase 1: scatter -d[i]*Z into sT (f32). sT row = bsL*128 + i_local.
    {
        float* sT = reinterpret_cast<float*>(esm);
        #pragma unroll
        for (int i = 0; i < 4; i++) {
            int rA = warpM * 64 + i * 16 + (lane >> 2);
            int rB = rA + 8;
            float dA = -sD[rA], dB = -sD[rB];
            #pragma unroll
            for (int j = 0; j < 4; j++) {
                int pl = warpN * 32 + j * 8 + (lane & 3) * 2;
                int bsL = pl >> 6, c = pl & 63;
                float* tA = sT + (bsL * 128 + rA) * EP_PAD + c;
                float* tB = sT + (bsL * 128 + rB) * EP_PAD + c;
                tA[0] = dA * acc[i][j][0];
                tA[1] = dA * acc[i][j][1];
                tB[0] = dB * acc[i][j][2];
                tB[1] = dB * acc[i][j][3];
            }
        }
    }
    __syncthreads();

    // ---- Phase 2: T += x, convert to tf32 in place (coalesced x reads)
    {
        float* sT = reinterpret_cast<float*>(esm);
        const int bsg0 = blockIdx.x * 2;
        for (int k = tid; k < 4096; k += 256) {
            int bsL = k >> 11, r = (k >> 4) & 127, c4 = k & 15;
            float4 xv = reinterpret_cast<const float4*>(x)
                [((u64)(bsg0 + bsL) * NN + bm0 + r) * 16 + c4];
            u32* d = esm + (bsL * 128 + r) * EP_PAD + c4 * 4;
            float* f = sT + (bsL * 128 + r) * EP_PAD + c4 * 4;
            float t0 = xv.x + f[0], t1 = xv.y + f[1];
            float t2 = xv.z + f[2], t3 = xv.w + f[3];
            d[0] = f2tf32(t0); d[1] = f2tf32(t1); d[2] = f2tf32(t2); d[3] = f2tf32(t3);
        }
    }
    __syncthreads();

    // ---- Phase 3: out = sigmoid(T @ W^T), warp = 32 rows (2 m16 tiles), all h
    {
        const u32* sT = esm;
        const u32* sW = esm + SW_OFF;
        const int gq = lane >> 2, tq = lane & 3;
        const int bsg = blockIdx.x * 2 + (wid >> 2);

        #pragma unroll 1
        for (int mt = 0; mt < 2; mt++) {
            const int rbase = wid * 32 + mt * 16;     // sT row base
            float acc2[16][4];
            #pragma unroll
            for (int nt = 0; nt < 16; nt++)
                #pragma unroll
                for (int q = 0; q < 4; q++) acc2[nt][q] = 0.f;

            const u32* tRow0 = sT + (rbase + gq) * EP_PAD;
            const u32* tRow8 = tRow0 + 8 * EP_PAD;

            #pragma unroll
            for (int ks = 0; ks < 8; ks++) {
                int k0 = ks * 8 + tq;
                u32 a0 = tRow0[k0];
                u32 a1 = tRow8[k0];
                u32 a2 = tRow0[k0 + 4];
                u32 a3 = tRow8[k0 + 4];
                #pragma unroll
                for (int nt = 0; nt < 16; nt++) {
                    const u32* wRow = sW + (nt * 8 + gq) * EP_PAD;
                    u32 b0 = wRow[k0];
                    u32 b1 = wRow[k0 + 4];
                    asm volatile("mma.sync.aligned.m16n8k8.row.col.f32.tf32.tf32.f32 "
                        "{%0,%1,%2,%3}, {%4,%5,%6,%7}, {%8,%9}, {%0,%1,%2,%3};"
                        : "+f"(acc2[nt][0]), "+f"(acc2[nt][1]),
                          "+f"(acc2[nt][2]), "+f"(acc2[nt][3])
                        : "r"(a0), "r"(a1), "r"(a2), "r"(a3), "r"(b0), "r"(b1));
                }
            }

            const int iA = bm0 + ((rbase & 127) + gq);
            float* oA = out + ((u64)bsg * NN + iA) * HH + tq * 2;
            float* oB = oA + (u64)8 * HH;
            #pragma unroll
            for (int nt = 0; nt < 16; nt++) {
                float2 v0, v1;
                v0.x = 1.0f / (1.0f + __expf(-acc2[nt][0]));
                v0.y = 1.0f / (1.0f + __expf(-acc2[nt][1]));
                v1.x = 1.0f / (1.0f + __expf(-acc2[nt][2]));
                v1.y = 1.0f / (1.0f + __expf(-acc2[nt][3]));
                *reinterpret_cast<float2*>(oA + nt * 8) = v0;
                *reinterpret_cast<float2*>(oB + nt * 8) = v1;
            }
        }
    }
}

// ---------------------------------------------------------------------------
extern "C" void kernel_launch(void* const* d_in, const int* in_sizes, int n_in,
                              void* d_out, int out_size) {
    const float* x = (const float*)d_in[0];
    const float* A = (const float*)d_in[1];
    const float* W = (const float*)d_in[2];
    float* out = (float*)d_out;

    const int out_elems = NB * NS * NN * HH;   // 25,165,824
    const int do_copy = (out_size >= out_elems + NN * NN) ? 1 : 0;
    float* tail = do_copy ? (out + out_elems) : (float*)g_xdT;  // dummy if absent

    cudaFuncSetAttribute(gemm_fused_kernel,
                         cudaFuncAttributeMaxDynamicSharedMemorySize, GEMM_DYN);

    fusedA_kernel<<<NN, 256>>>(A, tail, do_copy);

    {
        dim3 grid(NN / 64, BS);          // (64, 48)
        build_xdT_kernel<<<grid, 256>>>(x);
    }
    {
        dim3 grid(PP / 128, NN / 128);   // (24, 32)
        gemm_fused_kernel<<<grid, 256, GEMM_DYN>>>(x, W, out);
    }
}